// round 1
// baseline (speedup 1.0000x reference)
#include <cuda_runtime.h>
#include <math.h>

#define BB 2
#define SS 2048
#define DD 1024
#define NH 16
#define NKV 4
#define QKB 16
#define VB 32
#define NREP (NH / NKV)
#define MROWS (BB * SS)   // 4096

// Scratch (allocation-free rule: __device__ globals)
__device__ float g_pq[BB * NH * SS * QKB];    // [b,h,s,16]   4 MB
__device__ float g_pk[BB * NKV * SS * QKB];   // [b,kv,s,16]  1 MB
__device__ float g_pv[BB * NKV * SS * VB];    // [b,kv,s,32]  2 MB
__device__ float g_ovh[BB * SS * NH * VB];    // [b,s, h*32]  8 MB

// ---------------------------------------------------------------------------
// SGEMM: C[M,N] = A[M,K] @ W[K,N], both row-major.
// MODE 0: plain row-major store.
// MODE 1: sigmoid epilogue + scatter to [b, head, s, dd] layout
//         (head = n/dd, d = n%dd, b = m/SS, s = m%SS, nheads = N/dd).
// Block tile 64x64, K-tile 16, 256 threads, 4x4 per thread.
// Requires M%64==0, N%64==0, K%16==0 (true for all our shapes).
// ---------------------------------------------------------------------------
template <int MODE>
__global__ void __launch_bounds__(256) sgemm_kernel(
    const float* __restrict__ A, const float* __restrict__ W,
    float* __restrict__ C, int M, int N, int K, int dd)
{
    __shared__ float As[16][64];   // As[k][m]
    __shared__ float Bs[16][64];   // Bs[k][n]

    const int tid = threadIdx.x;
    const int tx = tid & 15;        // 0..15 -> n
    const int ty = tid >> 4;        // 0..15 -> m
    const int row0 = blockIdx.y * 64;
    const int col0 = blockIdx.x * 64;

    // A-tile load mapping: 64 rows x 16 cols, one float4 per thread
    const int arow = tid >> 2;            // 0..63
    const int acol = (tid & 3) * 4;       // 0,4,8,12
    // B-tile load mapping: 16 rows x 64 cols, one float4 per thread
    const int brow = tid >> 4;            // 0..15
    const int bcol = (tid & 15) * 4;      // 0..60

    const float* Aptr = A + (size_t)(row0 + arow) * K + acol;
    const float* Wptr = W + (size_t)brow * N + col0 + bcol;

    float acc[4][4];
#pragma unroll
    for (int i = 0; i < 4; i++)
#pragma unroll
        for (int j = 0; j < 4; j++) acc[i][j] = 0.f;

    for (int kk = 0; kk < K; kk += 16) {
        float4 av = *(const float4*)Aptr;  Aptr += 16;
        float4 bv = *(const float4*)Wptr;  Wptr += (size_t)16 * N;

        As[acol + 0][arow] = av.x;
        As[acol + 1][arow] = av.y;
        As[acol + 2][arow] = av.z;
        As[acol + 3][arow] = av.w;
        *(float4*)&Bs[brow][bcol] = bv;
        __syncthreads();

#pragma unroll
        for (int k = 0; k < 16; k++) {
            float4 a4 = *(const float4*)&As[k][ty * 4];
            float4 b4 = *(const float4*)&Bs[k][tx * 4];
            float am[4] = {a4.x, a4.y, a4.z, a4.w};
            float bn[4] = {b4.x, b4.y, b4.z, b4.w};
#pragma unroll
            for (int i = 0; i < 4; i++)
#pragma unroll
                for (int j = 0; j < 4; j++)
                    acc[i][j] = fmaf(am[i], bn[j], acc[i][j]);
        }
        __syncthreads();
    }

    if (MODE == 0) {
#pragma unroll
        for (int i = 0; i < 4; i++) {
            int m = row0 + ty * 4 + i;
            float4 st = make_float4(acc[i][0], acc[i][1], acc[i][2], acc[i][3]);
            *(float4*)&C[(size_t)m * N + col0 + tx * 4] = st;
        }
    } else {
        const int nheads = N / dd;
#pragma unroll
        for (int i = 0; i < 4; i++) {
            int m = row0 + ty * 4 + i;
            int b = m / SS;
            int s = m - b * SS;
#pragma unroll
            for (int j = 0; j < 4; j++) {
                int n = col0 + tx * 4 + j;
                int head = n / dd;
                int d = n - head * dd;
                float v = 1.f / (1.f + __expf(-acc[i][j]));
                C[(((size_t)(b * nheads + head) * SS) + s) * dd + d] = v;
            }
        }
    }
}

// ---------------------------------------------------------------------------
// Streaming causal attention. One thread = one query (64 threads, 64 queries
// per CTA). Key insight: score = (QKB - sum(pq)) + sum_d (2*pq_d - 1)*pk_d,
// and score in [0,16] so no softmax max-subtraction is needed (fp32-safe).
// Epilogue fuses vh -> e0 + (e1-e0)*vh and writes [B,S,H*VB] row-major.
// ---------------------------------------------------------------------------
#define ATT_BM 64
#define ATT_BN 64

__global__ void __launch_bounds__(ATT_BM) rosa_attn_kernel(
    const float* __restrict__ pq, const float* __restrict__ pk,
    const float* __restrict__ pv, const float* __restrict__ e0,
    const float* __restrict__ e1, float* __restrict__ ovh)
{
    const int sblk = blockIdx.x;          // 0..31
    const int h    = blockIdx.y;          // 0..15
    const int b    = blockIdx.z;          // 0..1
    const int kvh  = h / NREP;
    const int tid  = threadIdx.x;
    const int s    = sblk * ATT_BM + tid;

    __shared__ float sk[ATT_BN][QKB];     // 4 KB
    __shared__ float sv[ATT_BN][VB];      // 8 KB

    // Load query, transform to qm = 2*pq - 1, c = QKB - sum(pq)
    const float* qrow = pq + (((size_t)(b * NH + h) * SS) + s) * QKB;
    float qm[QKB];
    float c = (float)QKB;
#pragma unroll
    for (int d = 0; d < QKB; d++) {
        float x = qrow[d];
        c -= x;
        qm[d] = 2.f * x - 1.f;
    }

    float num[VB];
#pragma unroll
    for (int d = 0; d < VB; d++) num[d] = 0.f;
    float den = 0.f;

    const float* pk_base = pk + ((size_t)(b * NKV + kvh) * SS) * QKB;
    const float* pv_base = pv + ((size_t)(b * NKV + kvh) * SS) * VB;

    const int ntiles = sblk + 1;
    for (int t = 0; t < ntiles; t++) {
        const int t0 = t * ATT_BN;
        __syncthreads();
        // Coalesced tile loads: both tiles are contiguous in gmem.
        {
            const float* kt = pk_base + (size_t)t0 * QKB;  // 1024 floats
            float* skf = &sk[0][0];
#pragma unroll
            for (int i = 0; i < (ATT_BN * QKB) / ATT_BM; i++)
                skf[i * ATT_BM + tid] = kt[i * ATT_BM + tid];
            const float* vt = pv_base + (size_t)t0 * VB;   // 2048 floats
            float* svf = &sv[0][0];
#pragma unroll
            for (int i = 0; i < (ATT_BN * VB) / ATT_BM; i++)
                svf[i * ATT_BM + tid] = vt[i * ATT_BM + tid];
        }
        __syncthreads();

        const int jmax = (t == sblk) ? (tid + 1) : ATT_BN;
        for (int j = 0; j < jmax; j++) {
            float dot = c;
#pragma unroll
            for (int d = 0; d < QKB; d++)
                dot = fmaf(qm[d], sk[j][d], dot);
            float p = __expf(dot);   // TAU = 1, score in [0,16]: no overflow
            den += p;
#pragma unroll
            for (int d = 0; d < VB; d++)
                num[d] = fmaf(p, sv[j][d], num[d]);
        }
    }

    const float inv = 1.f / den;
    float* orow = ovh + (((size_t)(b * SS + s) * NH) + h) * VB;
#pragma unroll
    for (int d = 0; d < VB; d++) {
        float vh = num[d] * inv;
        float a0 = e0[h * VB + d];
        float a1 = e1[h * VB + d];
        orow[d] = fmaf(a1 - a0, vh, a0);
    }
}

// ---------------------------------------------------------------------------
extern "C" void kernel_launch(void* const* d_in, const int* in_sizes, int n_in,
                              void* d_out, int out_size)
{
    const float* hs = (const float*)d_in[0];
    const float* Wq = (const float*)d_in[1];
    const float* Wk = (const float*)d_in[2];
    const float* Wv = (const float*)d_in[3];
    const float* Wo = (const float*)d_in[4];
    const float* e0 = (const float*)d_in[5];
    const float* e1 = (const float*)d_in[6];
    float* out = (float*)d_out;

    float *pq, *pk, *pv, *ovh;
    cudaGetSymbolAddress((void**)&pq,  g_pq);
    cudaGetSymbolAddress((void**)&pk,  g_pk);
    cudaGetSymbolAddress((void**)&pv,  g_pv);
    cudaGetSymbolAddress((void**)&ovh, g_ovh);

    // QKV projections with fused sigmoid + head scatter
    sgemm_kernel<1><<<dim3(256 / 64, MROWS / 64), 256>>>(hs, Wq, pq, MROWS, NH * QKB, DD, QKB);
    sgemm_kernel<1><<<dim3(64 / 64,  MROWS / 64), 256>>>(hs, Wk, pk, MROWS, NKV * QKB, DD, QKB);
    sgemm_kernel<1><<<dim3(128 / 64, MROWS / 64), 256>>>(hs, Wv, pv, MROWS, NKV * VB, DD, VB);

    // Causal streaming attention + value-embedding epilogue
    rosa_attn_kernel<<<dim3(SS / ATT_BM, NH, BB), ATT_BM>>>(pq, pk, pv, e0, e1, ovh);

    // Output projection
    sgemm_kernel<0><<<dim3(DD / 64, MROWS / 64), 256>>>(ovh, Wo, out, MROWS, DD, NH * VB, 0);
}